// round 14
// baseline (speedup 1.0000x reference)
#include <cuda_runtime.h>
#include <cstdint>

// Sliding-window (no-overlap) attention, mma.sync bf16-split, register-P,
// 2 CTAs/SM; streamed next-chunk ldcvt through the pair loop (strip-granular).
// B=4,S=8192,H=16,D=64,w=128,C=64. Block=(chunk,head,batch): 128 queries, 256 thr.
// d_out = out [B,S,H,64] then attn [B,S,H,384].

constexpr int Bc = 4, Sc = 8192, Hc = 16, Wn = 128, Cc = 64, NT = 256;

// smem offsets (bytes). rows: 144B stride (128B data + 16B pad).
constexpr uint32_t OFF_AH = 0;           // Q hi, then V hi [128][72] bf16
constexpr uint32_t OFF_AL = 18432;       // Q lo, then V lo
constexpr uint32_t OFF_KH = 36864;       // K hi [128 kpos][72]
constexpr uint32_t OFF_KL = 55296;       // K lo
constexpr uint32_t OFF_SSUM = 73728;     // 128 floats
constexpr uint32_t SMEM_BYTES = 73728 + 512;   // 74240 -> 2 CTAs/SM

__device__ __forceinline__ uint32_t su32(const void* p) {
    uint32_t a;
    asm("{ .reg .u64 t; cvta.to.shared.u64 t, %1; cvt.u32.u64 %0, t; }" : "=r"(a) : "l"(p));
    return a;
}
__device__ __forceinline__ void pack_split(float v0, float v1, uint32_t& hw, uint32_t& lw) {
    asm("cvt.rn.bf16x2.f32 %0, %1, %2;" : "=r"(hw) : "f"(v1), "f"(v0));
    float r0 = v0 - __uint_as_float(hw << 16);
    float r1 = v1 - __uint_as_float(hw & 0xffff0000u);
    asm("cvt.rn.bf16x2.f32 %0, %1, %2;" : "=r"(lw) : "f"(r1), "f"(r0));
}
__device__ __forceinline__ void ldsm4(uint32_t* r, uint32_t a) {
    asm volatile("ldmatrix.sync.aligned.m8n8.x4.shared.b16 {%0,%1,%2,%3}, [%4];"
        : "=r"(r[0]), "=r"(r[1]), "=r"(r[2]), "=r"(r[3]) : "r"(a));
}
__device__ __forceinline__ void ldsm4t(uint32_t* r, uint32_t a) {
    asm volatile("ldmatrix.sync.aligned.m8n8.x4.trans.shared.b16 {%0,%1,%2,%3}, [%4];"
        : "=r"(r[0]), "=r"(r[1]), "=r"(r[2]), "=r"(r[3]) : "r"(a));
}
__device__ __forceinline__ void mma_bf16(float* d, const uint32_t* a, const uint32_t* b) {
    asm volatile("mma.sync.aligned.m16n8k16.row.col.f32.bf16.bf16.f32 "
        "{%0,%1,%2,%3}, {%4,%5,%6,%7}, {%8,%9}, {%0,%1,%2,%3};"
        : "+f"(d[0]), "+f"(d[1]), "+f"(d[2]), "+f"(d[3])
        : "r"(a[0]), "r"(a[1]), "r"(a[2]), "r"(a[3]), "r"(b[0]), "r"(b[1]));
}

// fused LDG (fp32 128x64 tile) -> split-bf16 -> STS (prologue use)
__device__ __forceinline__ void ldcvt(const float* gb, char* smc,
                                      uint32_t oH, uint32_t oL, int tid) {
    #pragma unroll
    for (int i = 0; i < 2; i++) {
        float4 t[4];
        #pragma unroll
        for (int j = 0; j < 4; j++) {
            int f = tid + (i * 4 + j) * NT;
            t[j] = *(const float4*)(gb + (size_t)(f >> 4) * 1024 + (f & 15) * 4);
        }
        #pragma unroll
        for (int j = 0; j < 4; j++) {
            int f = tid + (i * 4 + j) * NT, row = f >> 4, g = f & 15;
            uint32_t h0, l0, h1, l1;
            pack_split(t[j].x, t[j].y, h0, l0);
            pack_split(t[j].z, t[j].w, h1, l1);
            *(uint2*)(smc + oH + row * 144 + g * 8) = make_uint2(h0, h1);
            *(uint2*)(smc + oL + row * 144 + g * 8) = make_uint2(l0, l1);
        }
    }
}
// chunk p LDG (strip rows 16p..16p+15): one float4/thread
__device__ __forceinline__ float4 ldg_chunk(const float* gb, int tid, int p) {
    int f = tid + p * NT;
    return *(const float4*)(gb + (size_t)(f >> 4) * 1024 + (f & 15) * 4);
}
// chunk p convert+STS into strip rows
__device__ __forceinline__ void sts_chunk(float4 t, char* smc, uint32_t oH, uint32_t oL,
                                          int tid, int p) {
    int f = tid + p * NT, row = f >> 4, g = f & 15;
    uint32_t h0, l0, h1, l1;
    pack_split(t.x, t.y, h0, l0);
    pack_split(t.z, t.w, h1, l1);
    *(uint2*)(smc + oH + row * 144 + g * 8) = make_uint2(h0, h1);
    *(uint2*)(smc + oL + row * 144 + g * 8) = make_uint2(l0, l1);
}

__global__ void __launch_bounds__(NT, 2)
swa_mma_kernel(const float* __restrict__ q, const float* __restrict__ k,
               const float* __restrict__ v, float* __restrict__ out,
               float* __restrict__ attn)
{
    extern __shared__ char smc[];
    const uint32_t sb = su32(smc);
    const int tid = threadIdx.x, wid = tid >> 5, lane = tid & 31;
    const int c = blockIdx.x, h = blockIdx.y, b = blockIdx.z;
    const int s0 = c * Wn;
    const int e0 = (c > 0) ? 0 : 1, e1 = (c < Cc - 1) ? 2 : 1;

    float* ssum = (float*)(smc + OFF_SSUM);
    if (tid < 128) ssum[tid] = 128.0f * (float)(e0 + 2 - e1);

    const size_t hb = (size_t)h * 64;
    const float* kbase = k + (size_t)(b * Sc) * 1024 + hb;
    const float* vbase = v + (size_t)(b * Sc) * 1024 + hb;

    // ---- prologue: Q -> bufA, fragments -> regs, then bufA becomes V ----
    ldcvt(q + (size_t)(b * Sc + s0) * 1024 + hb, smc, OFF_AH, OFF_AL, tid);
    __syncthreads();

    const int mrow = wid * 16;
    const int r0 = mrow + (lane >> 2);

    uint32_t ah[4][4], al[4][4];
    #pragma unroll
    for (int kt = 0; kt < 4; kt++) {
        uint32_t ab = (uint32_t)(mrow + (lane & 15)) * 144u +
                      (uint32_t)(kt * 16 + (lane >> 4) * 8) * 2u;
        ldsm4(ah[kt], sb + OFF_AH + ab);
        ldsm4(al[kt], sb + OFF_AL + ab);
    }
    __syncthreads();   // Q reads done; bufA now V

    // K(e0), V(e0) serial load (prologue only)
    ldcvt(kbase + (size_t)(c - 1 + e0) * Wn * 1024, smc, OFF_KH, OFF_KL, tid);
    ldcvt(vbase + (size_t)(c - 1 + e0) * Wn * 1024, smc, OFF_AH, OFF_AL, tid);
    __syncthreads();

    float o[8][4];
    #pragma unroll
    for (int i = 0; i < 8; i++) { o[i][0] = o[i][1] = o[i][2] = o[i][3] = 0.f; }

    float* aprow  = attn + ((size_t)(b * Sc + s0 + r0) * Hc + h) * 384;
    float* aprow8 = aprow + (size_t)8 * Hc * 384;

    for (int e = e0; e <= e1; e++) {
        const bool hn = (e < e1);                 // has next chunk
        const float* kn = kbase + (size_t)(c + e) * Wn * 1024;   // e+1 chunk
        const float* vn = vbase + (size_t)(c + e) * Wn * 1024;

        float4 kpre0, kpre1, vpre0, vpre1;        // rolling 2-chunk prefetch
        if (hn) {
            kpre0 = ldg_chunk(kn, tid, 0);  vpre0 = ldg_chunk(vn, tid, 0);
            kpre1 = ldg_chunk(kn, tid, 1);  vpre1 = ldg_chunk(vn, tid, 1);
        }

        float rs0 = 0.f, rs1 = 0.f;
        #pragma unroll
        for (int pair = 0; pair < 8; pair++) {
            // ---- QK strip (cols pair*16..+15), 3 split passes ----
            float sc0[4] = {0.f, 0.f, 0.f, 0.f};
            float sc1[4] = {0.f, 0.f, 0.f, 0.f};
            const int mat = lane >> 3;
            #pragma unroll
            for (int kt = 0; kt < 4; kt++) {
                uint32_t ba = (uint32_t)(pair * 16 + (mat >> 1) * 8 + (lane & 7)) * 144u +
                              (uint32_t)(kt * 16 + (mat & 1) * 8) * 2u;
                uint32_t bh[4], bl[4];
                ldsm4(bh, sb + OFF_KH + ba);
                ldsm4(bl, sb + OFF_KL + ba);
                mma_bf16(sc0, ah[kt], bh);     mma_bf16(sc1, ah[kt], bh + 2);
                mma_bf16(sc0, ah[kt], bl);     mma_bf16(sc1, ah[kt], bl + 2);
                mma_bf16(sc0, al[kt], bh);     mma_bf16(sc1, al[kt], bh + 2);
            }

            // ---- exp, row sums, unnormalized attn write, pack P frags ----
            float e00 = __expf(sc0[0]), e01 = __expf(sc0[1]);
            float e02 = __expf(sc0[2]), e03 = __expf(sc0[3]);
            float e10 = __expf(sc1[0]), e11 = __expf(sc1[1]);
            float e12 = __expf(sc1[2]), e13 = __expf(sc1[3]);
            rs0 += e00 + e01 + e10 + e11;
            rs1 += e02 + e03 + e12 + e13;
            const int col = e * 128 + pair * 16 + (lane & 3) * 2;
            *(float2*)(aprow  + col)     = make_float2(e00, e01);
            *(float2*)(aprow  + col + 8) = make_float2(e10, e11);
            *(float2*)(aprow8 + col)     = make_float2(e02, e03);
            *(float2*)(aprow8 + col + 8) = make_float2(e12, e13);
            uint32_t ph[4], pl[4];
            pack_split(e00, e01, ph[0], pl[0]);
            pack_split(e02, e03, ph[1], pl[1]);
            pack_split(e10, e11, ph[2], pl[2]);
            pack_split(e12, e13, ph[3], pl[3]);

            // ---- PV(pair): kpos strip against V (bufA), 3 split passes ----
            #pragma unroll
            for (int nvp = 0; nvp < 4; nvp++) {
                uint32_t va = (uint32_t)(pair * 16 + (lane & 15)) * 144u +
                              (uint32_t)(nvp * 16 + (lane >> 4) * 8) * 2u;
                uint32_t vh[4], vl[4];
                ldsm4t(vh, sb + OFF_AH + va);
                ldsm4t(vl, sb + OFF_AL + va);
                mma_bf16(o[2 * nvp],     ph, vh);     mma_bf16(o[2 * nvp + 1], ph, vh + 2);
                mma_bf16(o[2 * nvp],     ph, vl);     mma_bf16(o[2 * nvp + 1], ph, vl + 2);
                mma_bf16(o[2 * nvp],     pl, vh);     mma_bf16(o[2 * nvp + 1], pl, vh + 2);
            }

            // ---- strip p of this e fully consumed by every warp after this bar ----
            __syncthreads();
            if (hn) {
                // overwrite strip p with chunk p of e+1; refill prefetch slot
                if (pair & 1) {
                    sts_chunk(kpre1, smc, OFF_KH, OFF_KL, tid, pair);
                    sts_chunk(vpre1, smc, OFF_AH, OFF_AL, tid, pair);
                    if (pair < 6) {
                        kpre1 = ldg_chunk(kn, tid, pair + 2);
                        vpre1 = ldg_chunk(vn, tid, pair + 2);
                    }
                } else {
                    sts_chunk(kpre0, smc, OFF_KH, OFF_KL, tid, pair);
                    sts_chunk(vpre0, smc, OFF_AH, OFF_AL, tid, pair);
                    if (pair < 6) {
                        kpre0 = ldg_chunk(kn, tid, pair + 2);
                        vpre0 = ldg_chunk(vn, tid, pair + 2);
                    }
                }
            }
        }

        rs0 += __shfl_xor_sync(0xffffffffu, rs0, 1);
        rs0 += __shfl_xor_sync(0xffffffffu, rs0, 2);
        rs1 += __shfl_xor_sync(0xffffffffu, rs1, 1);
        rs1 += __shfl_xor_sync(0xffffffffu, rs1, 2);
        if ((lane & 3) == 0) {
            atomicAdd(&ssum[r0], rs0);
            atomicAdd(&ssum[r0 + 8], rs1);
        }
    }
    __syncthreads();   // ssum complete + visible

    // ---- out = O * inv ----
    {
        const float i0 = 1.0f / ssum[r0], i8 = 1.0f / ssum[r0 + 8];
        float* ob  = out + ((size_t)(b * Sc + s0 + r0) * Hc + h) * 64;
        float* ob8 = ob + (size_t)8 * Hc * 64;
        #pragma unroll
        for (int nt = 0; nt < 8; nt++) {
            const int dim = nt * 8 + (lane & 3) * 2;
            *(float2*)(ob  + dim) = make_float2(o[nt][0] * i0, o[nt][1] * i0);
            *(float2*)(ob8 + dim) = make_float2(o[nt][2] * i8, o[nt][3] * i8);
        }
    }

    // ---- attn normalize pass: row-per-warp, fully coalesced float4 ----
    {
        #pragma unroll 2
        for (int rr = 0; rr < 16; rr++) {
            const int row = mrow + rr;
            const float inv = 1.0f / ssum[row];
            float* ar = attn + ((size_t)(b * Sc + s0 + row) * Hc + h) * 384;
            #pragma unroll
            for (int t = 0; t < 3; t++) {
                const int col = t * 128 + lane * 4;   // t == e index
                float4 oval;
                if (t < e0 || t > e1) {
                    oval = make_float4(inv, inv, inv, inv);
                } else {
                    oval = *(const float4*)(ar + col);
                    oval.x *= inv; oval.y *= inv; oval.z *= inv; oval.w *= inv;
                }
                *(float4*)(ar + col) = oval;
            }
        }
    }
}

extern "C" void kernel_launch(void* const* d_in, const int* in_sizes, int n_in,
                              void* d_out, int out_size)
{
    const float* q = (const float*)d_in[0];
    const float* k = (const float*)d_in[1];
    const float* v = (const float*)d_in[2];
    float* out  = (float*)d_out;
    float* attn = out + (size_t)Bc * Sc * Hc * 64;

    cudaFuncSetAttribute(swa_mma_kernel,
                         cudaFuncAttributeMaxDynamicSharedMemorySize, SMEM_BYTES);
    dim3 grid(Cc, Hc, Bc);
    swa_mma_kernel<<<grid, NT, SMEM_BYTES>>>(q, k, v, out, attn);
}

// round 15
// speedup vs baseline: 1.0705x; 1.0705x over previous
#include <cuda_runtime.h>
#include <cstdint>

// Sliding-window (no-overlap) attention, mma.sync bf16-split, register-P,
// 2 CTAs/SM; shuffle-coalesced attn stores (STG.128), serial per-e ldcvt (R13 base).
// B=4,S=8192,H=16,D=64,w=128,C=64. Block=(chunk,head,batch): 128 queries, 256 thr.
// d_out = out [B,S,H,64] then attn [B,S,H,384].

constexpr int Bc = 4, Sc = 8192, Hc = 16, Wn = 128, Cc = 64, NT = 256;

// smem offsets (bytes). rows: 144B stride (128B data + 16B pad).
constexpr uint32_t OFF_AH = 0;           // Q hi, then V hi [128][72] bf16
constexpr uint32_t OFF_AL = 18432;       // Q lo, then V lo
constexpr uint32_t OFF_KH = 36864;       // K hi [128 kpos][72]
constexpr uint32_t OFF_KL = 55296;       // K lo
constexpr uint32_t OFF_SSUM = 73728;     // 128 floats
constexpr uint32_t SMEM_BYTES = 73728 + 512;   // 74240 -> 2 CTAs/SM

__device__ __forceinline__ uint32_t su32(const void* p) {
    uint32_t a;
    asm("{ .reg .u64 t; cvta.to.shared.u64 t, %1; cvt.u32.u64 %0, t; }" : "=r"(a) : "l"(p));
    return a;
}
__device__ __forceinline__ void pack_split(float v0, float v1, uint32_t& hw, uint32_t& lw) {
    asm("cvt.rn.bf16x2.f32 %0, %1, %2;" : "=r"(hw) : "f"(v1), "f"(v0));
    float r0 = v0 - __uint_as_float(hw << 16);
    float r1 = v1 - __uint_as_float(hw & 0xffff0000u);
    asm("cvt.rn.bf16x2.f32 %0, %1, %2;" : "=r"(lw) : "f"(r1), "f"(r0));
}
__device__ __forceinline__ void ldsm4(uint32_t* r, uint32_t a) {
    asm volatile("ldmatrix.sync.aligned.m8n8.x4.shared.b16 {%0,%1,%2,%3}, [%4];"
        : "=r"(r[0]), "=r"(r[1]), "=r"(r[2]), "=r"(r[3]) : "r"(a));
}
__device__ __forceinline__ void ldsm4t(uint32_t* r, uint32_t a) {
    asm volatile("ldmatrix.sync.aligned.m8n8.x4.trans.shared.b16 {%0,%1,%2,%3}, [%4];"
        : "=r"(r[0]), "=r"(r[1]), "=r"(r[2]), "=r"(r[3]) : "r"(a));
}
__device__ __forceinline__ void mma_bf16(float* d, const uint32_t* a, const uint32_t* b) {
    asm volatile("mma.sync.aligned.m16n8k16.row.col.f32.bf16.bf16.f32 "
        "{%0,%1,%2,%3}, {%4,%5,%6,%7}, {%8,%9}, {%0,%1,%2,%3};"
        : "+f"(d[0]), "+f"(d[1]), "+f"(d[2]), "+f"(d[3])
        : "r"(a[0]), "r"(a[1]), "r"(a[2]), "r"(a[3]), "r"(b[0]), "r"(b[1]));
}

// fused LDG (fp32 128x64 tile) -> split-bf16 -> STS, transient 16-reg staging
__device__ __forceinline__ void ldcvt(const float* gb, char* smc,
                                      uint32_t oH, uint32_t oL, int tid) {
    #pragma unroll
    for (int i = 0; i < 2; i++) {
        float4 t[4];
        #pragma unroll
        for (int j = 0; j < 4; j++) {
            int f = tid + (i * 4 + j) * NT;
            t[j] = *(const float4*)(gb + (size_t)(f >> 4) * 1024 + (f & 15) * 4);
        }
        #pragma unroll
        for (int j = 0; j < 4; j++) {
            int f = tid + (i * 4 + j) * NT, row = f >> 4, g = f & 15;
            uint32_t h0, l0, h1, l1;
            pack_split(t[j].x, t[j].y, h0, l0);
            pack_split(t[j].z, t[j].w, h1, l1);
            *(uint2*)(smc + oH + row * 144 + g * 8) = make_uint2(h0, h1);
            *(uint2*)(smc + oL + row * 144 + g * 8) = make_uint2(l0, l1);
        }
    }
}

__global__ void __launch_bounds__(NT, 2)
swa_mma_kernel(const float* __restrict__ q, const float* __restrict__ k,
               const float* __restrict__ v, float* __restrict__ out,
               float* __restrict__ attn)
{
    extern __shared__ char smc[];
    const uint32_t sb = su32(smc);
    const int tid = threadIdx.x, wid = tid >> 5, lane = tid & 31;
    const int c = blockIdx.x, h = blockIdx.y, b = blockIdx.z;
    const int s0 = c * Wn;
    const int e0 = (c > 0) ? 0 : 1, e1 = (c < Cc - 1) ? 2 : 1;

    float* ssum = (float*)(smc + OFF_SSUM);
    if (tid < 128) ssum[tid] = 128.0f * (float)(e0 + 2 - e1);

    const size_t hb = (size_t)h * 64;
    const float* kbase = k + (size_t)(b * Sc) * 1024 + hb;
    const float* vbase = v + (size_t)(b * Sc) * 1024 + hb;

    // ---- prologue: Q -> bufA, fragments -> regs, then bufA freed for V ----
    ldcvt(q + (size_t)(b * Sc + s0) * 1024 + hb, smc, OFF_AH, OFF_AL, tid);
    __syncthreads();

    const int mrow = wid * 16;
    const int r0 = mrow + (lane >> 2);

    uint32_t ah[4][4], al[4][4];
    #pragma unroll
    for (int kt = 0; kt < 4; kt++) {
        uint32_t ab = (uint32_t)(mrow + (lane & 15)) * 144u +
                      (uint32_t)(kt * 16 + (lane >> 4) * 8) * 2u;
        ldsm4(ah[kt], sb + OFF_AH + ab);
        ldsm4(al[kt], sb + OFF_AL + ab);
    }
    __syncthreads();   // all warps done reading Q; bufA now V staging

    float o[8][4];
    #pragma unroll
    for (int i = 0; i < 8; i++) { o[i][0] = o[i][1] = o[i][2] = o[i][3] = 0.f; }

    // coalesced-store column offset within a 16-col pair strip:
    // even lanes cover cols 0-7, odd lanes cols 8-15 (float4 each, via shfl_xor(1))
    const int colOff = (lane & 1) * 8 + (lane & 2) * 2;
    float* aprow  = attn + ((size_t)(b * Sc + s0 + r0) * Hc + h) * 384;
    float* aprow8 = aprow + (size_t)8 * Hc * 384;

    float rs0 = 0.f, rs1 = 0.f;   // accumulated across all e

    for (int e = e0; e <= e1; e++) {
        // K(e) -> bufK, V(e) -> bufA (L2-hot: shared across 16 heads)
        ldcvt(kbase + (size_t)(c - 1 + e) * Wn * 1024, smc, OFF_KH, OFF_KL, tid);
        ldcvt(vbase + (size_t)(c - 1 + e) * Wn * 1024, smc, OFF_AH, OFF_AL, tid);
        __syncthreads();   // tiles visible

        #pragma unroll
        for (int pair = 0; pair < 8; pair++) {
            // ---- QK strip (cols pair*16..+15), 3 split passes ----
            float sc0[4] = {0.f, 0.f, 0.f, 0.f};
            float sc1[4] = {0.f, 0.f, 0.f, 0.f};
            const int mat = lane >> 3;
            #pragma unroll
            for (int kt = 0; kt < 4; kt++) {
                uint32_t ba = (uint32_t)(pair * 16 + (mat >> 1) * 8 + (lane & 7)) * 144u +
                              (uint32_t)(kt * 16 + (mat & 1) * 8) * 2u;
                uint32_t bh[4], bl[4];
                ldsm4(bh, sb + OFF_KH + ba);
                ldsm4(bl, sb + OFF_KL + ba);
                mma_bf16(sc0, ah[kt], bh);     mma_bf16(sc1, ah[kt], bh + 2);
                mma_bf16(sc0, ah[kt], bl);     mma_bf16(sc1, ah[kt], bl + 2);
                mma_bf16(sc0, al[kt], bh);     mma_bf16(sc1, al[kt], bh + 2);
            }

            // ---- exp + row sums ----
            float e00 = __expf(sc0[0]), e01 = __expf(sc0[1]);
            float e02 = __expf(sc0[2]), e03 = __expf(sc0[3]);
            float e10 = __expf(sc1[0]), e11 = __expf(sc1[1]);
            float e12 = __expf(sc1[2]), e13 = __expf(sc1[3]);
            rs0 += e00 + e01 + e10 + e11;
            rs1 += e02 + e03 + e12 + e13;

            // ---- shuffle-coalesced unnormalized attn store (2x STG.128) ----
            {
                const int cb = e * 128 + pair * 16 + colOff;
                // row r0 group: even lane -> {e00,e01,nb(e00),nb(e01)}, odd -> {nb(e10),nb(e11),e10,e11}
                float x0 = __shfl_xor_sync(0xffffffffu, e00, 1);
                float x1 = __shfl_xor_sync(0xffffffffu, e01, 1);
                float y0 = __shfl_xor_sync(0xffffffffu, e10, 1);
                float y1 = __shfl_xor_sync(0xffffffffu, e11, 1);
                float4 f0 = (lane & 1) ? make_float4(y0, y1, e10, e11)
                                       : make_float4(e00, e01, x0, x1);
                *(float4*)(aprow + cb) = f0;
                // row r0+8 group
                float u0 = __shfl_xor_sync(0xffffffffu, e02, 1);
                float u1 = __shfl_xor_sync(0xffffffffu, e03, 1);
                float w0 = __shfl_xor_sync(0xffffffffu, e12, 1);
                float w1 = __shfl_xor_sync(0xffffffffu, e13, 1);
                float4 f1 = (lane & 1) ? make_float4(w0, w1, e12, e13)
                                       : make_float4(e02, e03, u0, u1);
                *(float4*)(aprow8 + cb) = f1;
            }

            // ---- pack P frags ----
            uint32_t ph[4], pl[4];
            pack_split(e00, e01, ph[0], pl[0]);
            pack_split(e02, e03, ph[1], pl[1]);
            pack_split(e10, e11, ph[2], pl[2]);
            pack_split(e12, e13, ph[3], pl[3]);

            // ---- PV(pair): kpos strip against V (bufA), 3 split passes ----
            #pragma unroll
            for (int nvp = 0; nvp < 4; nvp++) {
                uint32_t va = (uint32_t)(pair * 16 + (lane & 15)) * 144u +
                              (uint32_t)(nvp * 16 + (lane >> 4) * 8) * 2u;
                uint32_t vh[4], vl[4];
                ldsm4t(vh, sb + OFF_AH + va);
                ldsm4t(vl, sb + OFF_AL + va);
                mma_bf16(o[2 * nvp],     ph, vh);     mma_bf16(o[2 * nvp + 1], ph, vh + 2);
                mma_bf16(o[2 * nvp],     ph, vl);     mma_bf16(o[2 * nvp + 1], ph, vl + 2);
                mma_bf16(o[2 * nvp],     pl, vh);     mma_bf16(o[2 * nvp + 1], pl, vh + 2);
            }
        }
        __syncthreads();   // K/V reads done before next e's ldcvt overwrites
    }

    // ---- row sums: one reduce + one atomic per warp ----
    rs0 += __shfl_xor_sync(0xffffffffu, rs0, 1);
    rs0 += __shfl_xor_sync(0xffffffffu, rs0, 2);
    rs1 += __shfl_xor_sync(0xffffffffu, rs1, 1);
    rs1 += __shfl_xor_sync(0xffffffffu, rs1, 2);
    if ((lane & 3) == 0) {
        atomicAdd(&ssum[r0], rs0);
        atomicAdd(&ssum[r0 + 8], rs1);
    }
    __syncthreads();   // ssum complete + visible

    // ---- out = O * inv ----
    {
        const float i0 = 1.0f / ssum[r0], i8 = 1.0f / ssum[r0 + 8];
        float* ob  = out + ((size_t)(b * Sc + s0 + r0) * Hc + h) * 64;
        float* ob8 = ob + (size_t)8 * Hc * 64;
        #pragma unroll
        for (int nt = 0; nt < 8; nt++) {
            const int dim = nt * 8 + (lane & 3) * 2;
            *(float2*)(ob  + dim) = make_float2(o[nt][0] * i0, o[nt][1] * i0);
            *(float2*)(ob8 + dim) = make_float2(o[nt][2] * i8, o[nt][3] * i8);
        }
    }

    // ---- attn normalize pass: row-per-warp, fully coalesced float4 ----
    {
        #pragma unroll 2
        for (int rr = 0; rr < 16; rr++) {
            const int row = mrow + rr;
            const float inv = 1.0f / ssum[row];
            float* ar = attn + ((size_t)(b * Sc + s0 + row) * Hc + h) * 384;
            #pragma unroll
            for (int t = 0; t < 3; t++) {
                const int col = t * 128 + lane * 4;   // t == e index
                float4 oval;
                if (t < e0 || t > e1) {
                    oval = make_float4(inv, inv, inv, inv);
                } else {
                    oval = *(const float4*)(ar + col);
                    oval.x *= inv; oval.y *= inv; oval.z *= inv; oval.w *= inv;
                }
                *(float4*)(ar + col) = oval;
            }
        }
    }
}

extern "C" void kernel_launch(void* const* d_in, const int* in_sizes, int n_in,
                              void* d_out, int out_size)
{
    const float* q = (const float*)d_in[0];
    const float* k = (const float*)d_in[1];
    const float* v = (const float*)d_in[2];
    float* out  = (float*)d_out;
    float* attn = out + (size_t)Bc * Sc * Hc * 64;

    cudaFuncSetAttribute(swa_mma_kernel,
                         cudaFuncAttributeMaxDynamicSharedMemorySize, SMEM_BYTES);
    dim3 grid(Cc, Hc, Bc);
    swa_mma_kernel<<<grid, NT, SMEM_BYTES>>>(q, k, v, out, attn);
}